// round 7
// baseline (speedup 1.0000x reference)
#include <cuda_runtime.h>
#include <math.h>

#define cB 8
#define cN 1024
#define cD 768
#define cX 1536
#define cH 3
#define NB (cB*cN)      // 8192
#define LISTCAP 64

// ---------------- scratch (static device globals; no allocations) ----------------
static __device__ float g_denom[NB];
static __device__ float g_ax[NB*cD];
static __device__ float g_t1[NB*cD];
static __device__ float g_t2[NB*cD];
static __device__ float g_out1[NB*cD];
static __device__ float g_conve[NB*cD];
static __device__ float g_wk[3*cN*cN];
static __device__ float g_x[NB*cX];
static __device__ float g_q[NB*cX];
static __device__ float g_k[NB*cX];
static __device__ float g_attn[(size_t)cB*cH*cN*cN];
static __device__ float g_rowsum[cB*cH*cN];
static __device__ float g_hsum[cB*cH];
static __device__ int   g_midx[cB];
static __device__ float g_cand[cB*32*2];
static __device__ float g_thr[cB];
static __device__ int   g_cnt[cB];
static __device__ int   g_list[cB*LISTCAP];
static __device__ int   g_nr[cB];
static __device__ int   g_ne[cB];
static __device__ int   g_rows[cB*LISTCAP];
static __device__ float g_dn2[cB*LISTCAP];
static __device__ int   g_eslot[cB*LISTCAP];
static __device__ int   g_ej[cB*LISTCAP];
static __device__ float g_eval[cB*LISTCAP];
static __device__ float g_ax2[cB*LISTCAP*cX];
static __device__ float g_out3[NB*cD];
static __device__ float g_hbuf[NB*cD];

// packed f32x2 FMA: two independent fp32 rn FMAs per issue (FFMA2).
// Carried in unsigned long long (the "l" asm constraint requires a 64-bit
// integer operand; the bits are two packed fp32 lanes).
typedef unsigned long long u64;
__device__ __forceinline__ u64 ffma2(u64 a, u64 b, u64 c) {
    u64 d;
    asm("fma.rn.f32x2 %0, %1, %2, %3;" : "=l"(d) : "l"(a), "l"(b), "l"(c));
    return d;
}

// ---------------- GEMM: C = alpha * A @ op(B) (+bias) (+C) (relu) ----------------
// BL==0: B is [N,K] row-major (C[m,n] = sum_k A[m,k]*B[n,k])  -- "NT"
// BL==1: B is [K,N] row-major (C[m,n] = sum_k A[m,k]*B[k,n])  -- "NN"
// z = blockIdx.z; z1 = z/zmod, z2 = z%zmod; each operand offset = z1*s1 + z2*s2.
template<int BL>
__global__ __launch_bounds__(256)
void gemm_k(const float* __restrict__ A, const float* __restrict__ Bm,
            float* __restrict__ C,
            int M, int Nn, int K, int lda, int ldb, int ldc, int zmod,
            long long sA1, long long sA2, long long sB1, long long sB2,
            long long sC1, long long sC2,
            float alpha, const float* __restrict__ bias, int biasMode,
            int beta, int relu)
{
    __shared__ __align__(16) float As2[16][264];   // duplicated: [k][2m],[2m+1] = A[m][k]
    __shared__ __align__(16) float Bs[16][132];
    int z = blockIdx.z, z1 = z / zmod, z2 = z - z1 * zmod;
    A  += z1 * sA1 + z2 * sA2;
    Bm += z1 * sB1 + z2 * sB2;
    C  += z1 * sC1 + z2 * sC2;
    int bm = blockIdx.y * 128, bn = blockIdx.x * 128;
    int tid = threadIdx.x, tx = tid & 15, ty = tid >> 4;

    u64 acc[8][4];
    #pragma unroll
    for (int i = 0; i < 8; i++)
        #pragma unroll
        for (int j = 0; j < 4; j++) acc[i][j] = 0ull;   // two packed fp32 zeros

    for (int kb = 0; kb < K; kb += 16) {
        {   // A tile: 128 rows x 16 k, duplicated into As2[k][2r],[2r+1]
            int r = tid >> 1, kc = (tid & 1) * 8;
            int gm = bm + r;
            #pragma unroll
            for (int i = 0; i < 8; i++) {
                int gk = kb + kc + i;
                float v = (gm < M && gk < K) ? A[(long long)gm * lda + gk] : 0.f;
                As2[kc + i][2 * r]     = v;
                As2[kc + i][2 * r + 1] = v;
            }
        }
        if (BL == 0) {  // B [N,K]
            int r = tid >> 1, kc = (tid & 1) * 8;
            int gn = bn + r;
            #pragma unroll
            for (int i = 0; i < 8; i++) {
                int gk = kb + kc + i;
                Bs[kc + i][r] = (gn < Nn && gk < K) ? Bm[(long long)gn * ldb + gk] : 0.f;
            }
        } else {        // B [K,N]
            int kr = tid >> 4, nc = (tid & 15) * 8;
            int gk = kb + kr;
            #pragma unroll
            for (int i = 0; i < 8; i++) {
                int gn = bn + nc + i;
                Bs[kr][nc + i] = (gk < K && gn < Nn) ? Bm[(long long)gk * ldb + gn] : 0.f;
            }
        }
        __syncthreads();
        #pragma unroll
        for (int k = 0; k < 16; k++) {
            ulonglong2 A0 = *(const ulonglong2*)&As2[k][ty * 8];
            ulonglong2 A1 = *(const ulonglong2*)&As2[k][ty * 8 + 4];
            ulonglong2 A2 = *(const ulonglong2*)&As2[k][128 + ty * 8];
            ulonglong2 A3 = *(const ulonglong2*)&As2[k][128 + ty * 8 + 4];
            ulonglong2 B0 = *(const ulonglong2*)&Bs[k][tx * 4];
            ulonglong2 B1 = *(const ulonglong2*)&Bs[k][64 + tx * 4];
            u64 ad[8] = {A0.x, A0.y, A1.x, A1.y, A2.x, A2.y, A3.x, A3.y};
            u64 bp[4] = {B0.x, B0.y, B1.x, B1.y};
            #pragma unroll
            for (int i = 0; i < 8; i++)
                #pragma unroll
                for (int jp = 0; jp < 4; jp++)
                    acc[i][jp] = ffma2(ad[i], bp[jp], acc[i][jp]);
        }
        __syncthreads();
    }
    #pragma unroll
    for (int i = 0; i < 8; i++) {
        int gm = bm + ((i < 4) ? ty * 4 + i : 64 + ty * 4 + (i - 4));
        if (gm >= M) continue;
        #pragma unroll
        for (int jp = 0; jp < 4; jp++) {
            #pragma unroll
            for (int h = 0; h < 2; h++) {
                int gn = bn + ((jp < 2) ? tx * 4 + jp * 2 + h
                                        : 64 + tx * 4 + (jp - 2) * 2 + h);
                if (gn >= Nn) continue;
                unsigned int bits = h ? (unsigned int)(acc[i][jp] >> 32)
                                      : (unsigned int)(acc[i][jp] & 0xFFFFFFFFu);
                float v = __uint_as_float(bits);
                v *= alpha;
                if (bias) v += biasMode ? bias[gm] : bias[gn];
                long long o = (long long)gm * ldc + gn;
                if (beta) v += C[o];
                if (relu) v = fmaxf(v, 0.f);
                C[o] = v;
            }
        }
    }
}

// ---------------- small kernels ----------------
__global__ void denom_kernel(const float* __restrict__ adj) {
    int row = blockIdx.x;
    const float* a = adj + (size_t)row * cN;
    int t = threadIdx.x;
    __shared__ float red[256];
    red[t] = (a[t] + a[t + 256]) + (a[t + 512] + a[t + 768]);
    __syncthreads();
    for (int k = 128; k > 0; k >>= 1) { if (t < k) red[t] += red[t + k]; __syncthreads(); }
    if (t == 0) g_denom[row] = red[0] + 1.f;
}

__global__ void combine1_kernel() {
    int idx = blockIdx.x * 256 + threadIdx.x;
    float d = g_denom[idx / cD];
    g_out1[idx] = fmaxf(g_t1[idx] / d, 0.f) + g_t2[idx];
}

__global__ void repack_kernel(const float* __restrict__ w) {
    int idx = blockIdx.x * 256 + threadIdx.x;   // o*1024+i, < 1048576
    #pragma unroll
    for (int kk = 0; kk < 3; kk++)
        g_wk[kk * (cN * cN) + idx] = w[(size_t)idx * 3 + kk];
}

__global__ void copyx_kernel(const float* __restrict__ inp) {
    int idx = blockIdx.x * 256 + threadIdx.x;   // over NB*cD
    int r = idx / cD, d = idx - r * cD;
    g_x[(size_t)r * cX + d] = inp[idx];
}

__global__ void softmax_kernel() {
    float* p = g_attn + (size_t)blockIdx.x * cN;
    int t = threadIdx.x;
    __shared__ float red[256];
    float v0 = p[t], v1 = p[t + 256], v2 = p[t + 512], v3 = p[t + 768];
    red[t] = fmaxf(fmaxf(v0, v1), fmaxf(v2, v3));
    __syncthreads();
    for (int k = 128; k > 0; k >>= 1) { if (t < k) red[t] = fmaxf(red[t], red[t + k]); __syncthreads(); }
    float m = red[0]; __syncthreads();
    v0 = expf(v0 - m); v1 = expf(v1 - m); v2 = expf(v2 - m); v3 = expf(v3 - m);
    red[t] = (v0 + v1) + (v2 + v3); __syncthreads();
    for (int k = 128; k > 0; k >>= 1) { if (t < k) red[t] += red[t + k]; __syncthreads(); }
    float Z = red[0]; __syncthreads();
    v0 /= Z; v1 /= Z; v2 /= Z; v3 /= Z;
    p[t] = v0; p[t + 256] = v1; p[t + 512] = v2; p[t + 768] = v3;
    red[t] = (v0 + v1) + (v2 + v3); __syncthreads();
    for (int k = 128; k > 0; k >>= 1) { if (t < k) red[t] += red[t + k]; __syncthreads(); }
    if (t == 0) g_rowsum[blockIdx.x] = red[0];
}

__global__ void headsum_kernel() {
    int bh = blockIdx.x, t = threadIdx.x;
    const float* r = g_rowsum + bh * cN;
    __shared__ float red[256];
    red[t] = (r[t] + r[t + 256]) + (r[t + 512] + r[t + 768]);
    __syncthreads();
    for (int k = 128; k > 0; k >>= 1) { if (t < k) red[t] += red[t + k]; __syncthreads(); }
    if (t == 0) g_hsum[bh] = red[0];
}

__global__ void choose_kernel() {
    if (threadIdx.x || blockIdx.x) return;
    float pr[cB][cH];
    for (int h = 0; h < cH; h++) {
        float M = -3.4e38f;
        for (int b = 0; b < cB; b++) M = fmaxf(M, g_hsum[b * cH + h]);
        float Dn = 0.f;
        for (int b = 0; b < cB; b++) Dn += expf(g_hsum[b * cH + h] - M);
        for (int b = 0; b < cB; b++) pr[b][h] = expf(g_hsum[b * cH + h] - M) / Dn;
    }
    for (int b = 0; b < cB; b++) {
        int mi = 0;
        if (pr[b][1] > pr[b][mi]) mi = 1;
        if (pr[b][2] > pr[b][mi]) mi = 2;
        g_midx[b] = mi;   // first-max-wins, matches jnp.argmax
    }
}

__device__ __forceinline__ void t2merge(float& m1, float& m2, float b1, float b2) {
    if (b1 > m1) { m2 = fmaxf(m1, b2); m1 = b1; } else { m2 = fmaxf(m2, b1); }
}

__global__ void top2a_kernel() {
    int bx = blockIdx.x; int b = bx >> 5, c = bx & 31;
    const float* p = g_attn + (size_t)(b * cH + g_midx[b]) * (size_t)(cN * cN)
                            + (size_t)c * 32768;
    float m1 = -3.4e38f, m2 = -3.4e38f;
    for (int i = threadIdx.x; i < 32768; i += 256) {
        float v = p[i];
        if (v > m1) { m2 = m1; m1 = v; } else if (v > m2) m2 = v;
    }
    __shared__ float s1[256], s2[256];
    int t = threadIdx.x;
    s1[t] = m1; s2[t] = m2; __syncthreads();
    for (int k = 128; k > 0; k >>= 1) {
        if (t < k) t2merge(s1[t], s2[t], s1[t + k], s2[t + k]);
        __syncthreads();
    }
    if (t == 0) { g_cand[bx * 2] = s1[0]; g_cand[bx * 2 + 1] = s2[0]; }
}

__global__ void top2b_kernel() {
    int b = blockIdx.x;
    if (threadIdx.x == 0) {
        float m1 = -3.4e38f, m2 = -3.4e38f;
        for (int c = 0; c < 32; c++)
            t2merge(m1, m2, g_cand[(b * 32 + c) * 2], g_cand[(b * 32 + c) * 2 + 1]);
        g_thr[b] = m2;   // 2nd-largest with multiplicity == top_k(flat,2)[..,-1]
        g_cnt[b] = 0;
    }
}

__global__ void build_kernel() {
    int bx = blockIdx.x; int b = bx >> 5, c = bx & 31;
    const float* p = g_attn + (size_t)(b * cH + g_midx[b]) * (size_t)(cN * cN);
    size_t base = (size_t)c * 32768;
    float thr = g_thr[b];
    for (int i = threadIdx.x; i < 32768; i += 256) {
        if (p[base + i] >= thr) {
            int pos = atomicAdd(&g_cnt[b], 1);
            if (pos < LISTCAP) g_list[b * LISTCAP + pos] = (int)(base + i);
        }
    }
}

__global__ void process_kernel() {
    int b = blockIdx.x;
    if (threadIdx.x) return;
    int n = g_cnt[b]; if (n > LISTCAP) n = LISTCAP;
    int* L = &g_list[b * LISTCAP];
    for (int i = 1; i < n; i++) {           // deterministic order
        int key = L[i], j = i - 1;
        while (j >= 0 && L[j] > key) { L[j + 1] = L[j]; j--; }
        L[j + 1] = key;
    }
    int nr = 0, ne = 0;
    for (int e = 0; e < n; e++) {
        int code = L[e], i = code >> 10, j = code & 1023;
        float val;
        if (i == j) val = 1.f;
        else {
            int rc = (j << 10) | i; bool f = false;
            for (int q2 = 0; q2 < n; q2++) if (L[q2] == rc) { f = true; break; }
            val = f ? 2.f : 1.f;            // (binm + binm^T, diag->1) * binm
        }
        int slot = -1;
        for (int r = 0; r < nr; r++) if (g_rows[b * LISTCAP + r] == i) { slot = r; break; }
        if (slot < 0) {
            slot = nr; g_rows[b * LISTCAP + nr] = i; g_dn2[b * LISTCAP + nr] = 1.f; nr++;
        }
        g_dn2[b * LISTCAP + slot] += val;   // denom2 = rowsum + 1
        g_eslot[b * LISTCAP + ne] = slot;
        g_ej[b * LISTCAP + ne] = j;
        g_eval[b * LISTCAP + ne] = val;
        ne++;
    }
    g_nr[b] = nr; g_ne[b] = ne;
}

__global__ void sparse_ax_kernel() {
    int bid = blockIdx.x; int b = bid / LISTCAP, slot = bid - b * LISTCAP;
    if (slot >= g_nr[b]) return;
    int ne = g_ne[b];
    for (int c = threadIdx.x; c < cX; c += 256) {
        float acc = 0.f;
        for (int e = 0; e < ne; e++) {
            if (g_eslot[b * LISTCAP + e] == slot) {
                int j = g_ej[b * LISTCAP + e];
                acc += g_eval[b * LISTCAP + e] * g_x[(size_t)(b * cN + j) * cX + c];
            }
        }
        g_ax2[(size_t)bid * cX + c] = acc;
    }
}

__global__ void sparse_fix_kernel(const float* __restrict__ W1w,
                                  const float* __restrict__ W1b) {
    int bid = blockIdx.x; int b = bid / LISTCAP, slot = bid - b * LISTCAP;
    if (slot >= g_nr[b]) return;
    int row = g_rows[b * LISTCAP + slot];
    float dn = g_dn2[b * LISTCAP + slot];
    const float* ax = &g_ax2[(size_t)bid * cX];
    #pragma unroll
    for (int dd = 0; dd < 3; dd++) {
        int d = threadIdx.x + dd * 256;
        const float* w = W1w + (size_t)d * cX;
        float y = 0.f;
        for (int c = 0; c < cX; c++) y += ax[c] * w[c];
        float v = fmaxf((y + W1b[d]) / dn, 0.f);
        g_out3[(size_t)(b * cN + row) * cD + d] += v;
    }
}

// ---------------- host side ----------------
static void run_gemm(int BL, dim3 grid, const float* A, const float* Bm, float* C,
                     int M, int Nn, int K, int lda, int ldb, int ldc, int zmod,
                     long long sA1, long long sA2, long long sB1, long long sB2,
                     long long sC1, long long sC2,
                     float alpha, const float* bias, int biasMode, int beta, int relu)
{
    if (BL == 0)
        gemm_k<0><<<grid, 256>>>(A, Bm, C, M, Nn, K, lda, ldb, ldc, zmod,
                                 sA1, sA2, sB1, sB2, sC1, sC2, alpha, bias, biasMode, beta, relu);
    else
        gemm_k<1><<<grid, 256>>>(A, Bm, C, M, Nn, K, lda, ldb, ldc, zmod,
                                 sA1, sA2, sB1, sB2, sC1, sC2, alpha, bias, biasMode, beta, relu);
}

#define GS(p, sym) do { void* _t = 0; cudaGetSymbolAddress(&_t, sym); p = (float*)_t; } while (0)

extern "C" void kernel_launch(void* const* d_in, const int* in_sizes, int n_in,
                              void* d_out, int out_size)
{
    const float* adj      = (const float*)d_in[0];
    const float* inputs   = (const float*)d_in[1];
    const float* W0_w     = (const float*)d_in[3];
    const float* W0_b     = (const float*)d_in[4];
    const float* W1_w     = (const float*)d_in[5];
    const float* W1_b     = (const float*)d_in[6];
    const float* linc_w   = (const float*)d_in[7];
    const float* linc_b   = (const float*)d_in[8];
    const float* fc1_w    = (const float*)d_in[9];
    const float* fc2_w    = (const float*)d_in[10];
    const float* conv_w   = (const float*)d_in[11];
    const float* conv_b   = (const float*)d_in[12];
    const float* aq_w     = (const float*)d_in[13];
    const float* aq_b     = (const float*)d_in[14];
    const float* ak_w     = (const float*)d_in[15];
    const float* ak_b     = (const float*)d_in[16];
    float* out = (float*)d_out;

    float *pax, *pt1, *pt2, *pout1, *pconve, *pwk, *px, *pq, *pk, *pattn, *pout3, *phbuf;
    GS(pax, g_ax); GS(pt1, g_t1); GS(pt2, g_t2); GS(pout1, g_out1);
    GS(pconve, g_conve); GS(pwk, g_wk); GS(px, g_x); GS(pq, g_q); GS(pk, g_k);
    GS(pattn, g_attn); GS(pout3, g_out3); GS(phbuf, g_hbuf);

    const long long sND = (long long)cN * cD;        // 786432
    const long long sNX = (long long)cN * cX;
    const long long sNN = (long long)cN * cN;

    // 1) denom = adj.sum(2) + 1
    denom_kernel<<<NB, 256>>>(adj);

    // 2) Ax = adj @ inputs  (8 batches, NN layout)
    run_gemm(1, dim3(cD/128, cN/128, cB), adj, inputs, pax,
             cN, cD, cN, cN, cD, cD, 1, sNN, 0, sND, 0, sND, 0,
             1.f, 0, 0, 0, 0);

    // 3) t1 = Ax @ W0^T + b ; 4) t2 = inputs @ W0^T + b
    run_gemm(0, dim3(cD/128, NB/128, 1), pax, W0_w, pt1,
             NB, cD, cD, cD, cD, cD, 1, 0,0,0,0,0,0, 1.f, W0_b, 0, 0, 0);
    run_gemm(0, dim3(cD/128, NB/128, 1), inputs, W0_w, pt2,
             NB, cD, cD, cD, cD, cD, 1, 0,0,0,0,0,0, 1.f, W0_b, 0, 0, 0);

    // 5) out1 = relu(t1/denom) + t2
    combine1_kernel<<<NB*cD/256, 256>>>();

    // 6) conv: repack weights, 3 accumulated GEMMs (bias on k=0, relu on k=2)
    repack_kernel<<<(cN*cN)/256, 256>>>(conv_w);
    for (int kk = 0; kk < 3; kk++)
        run_gemm(1, dim3(6, cN/128, cB), pwk + (long long)kk*cN*cN, pout1 + kk, pconve,
                 cN, cD-2, cN, cN, cD, cD, 1, 0, 0, sND, 0, sND, 0,
                 1.f, (kk==0) ? conv_b : 0, 1, (kk>0), (kk==2));

    // 7) x = concat([inputs, linearc(conve)], -1)
    copyx_kernel<<<NB*cD/256, 256>>>(inputs);
    run_gemm(0, dim3(cD/128, NB/128, 1), pconve, linc_w, px + cD,
             NB, cD, cD-2, cD, cD-2, cX, 1, 0,0,0,0,0,0, 1.f, linc_b, 0, 0, 0);

    // 8) q, k projections
    run_gemm(0, dim3(cX/128, NB/128, 1), px, aq_w, pq,
             NB, cX, cX, cX, cX, cX, 1, 0,0,0,0,0,0, 1.f, aq_b, 0, 0, 0);
    run_gemm(0, dim3(cX/128, NB/128, 1), px, ak_w, pk,
             NB, cX, cX, cX, cX, cX, 1, 0,0,0,0,0,0, 1.f, ak_b, 0, 0, 0);

    // 9) scores: 24 (b,h) GEMMs in one launch, z = b*3+h
    run_gemm(0, dim3(cN/128, cN/128, cB*cH), pq, pk, pattn,
             cN, cN, 512, cX, cX, cN, cH,
             sNX, 512, sNX, 512, (long long)cH*sNN, sNN,
             0.044194173824159216f, 0, 0, 0, 0);

    // 10) softmax rows + rowsums + head sums + head choice
    softmax_kernel<<<cB*cH*cN, 256>>>();
    headsum_kernel<<<cB*cH, 256>>>();
    choose_kernel<<<1, 32>>>();

    // 11) global top-2 threshold + sparse adj2 edge list
    top2a_kernel<<<cB*32, 256>>>();
    top2b_kernel<<<cB, 32>>>();
    build_kernel<<<cB*32, 256>>>();
    process_kernel<<<cB, 32>>>();

    // 12) dense part of GCN layer 2: out3 = x @ W1^T + b
    run_gemm(0, dim3(cD/128, NB/128, 1), px, W1_w, pout3,
             NB, cD, cX, cX, cX, cD, 1, 0,0,0,0,0,0, 1.f, W1_b, 0, 0, 0);

    // 13) sparse correction: out3[row] += relu((adj2@x @ W1^T + b)/denom2)
    sparse_ax_kernel<<<cB*LISTCAP, 256>>>();
    sparse_fix_kernel<<<cB*LISTCAP, 256>>>(W1_w, W1_b);

    // 14) fc: out = fc2( relu(fc1(out3)) )
    run_gemm(0, dim3(cD/128, NB/128, 1), pout3, fc1_w, phbuf,
             NB, cD, cD, cD, cD, cD, 1, 0,0,0,0,0,0, 1.f, 0, 0, 0, 1);
    run_gemm(0, dim3(cD/128, NB/128, 1), phbuf, fc2_w, out,
             NB, cD, cD, cD, cD, cD, 1, 0,0,0,0,0,0, 1.f, 0, 0, 0, 0);
}

// round 10
// speedup vs baseline: 1.0244x; 1.0244x over previous
#include <cuda_runtime.h>
#include <math.h>

#define cB 8
#define cN 1024
#define cD 768
#define cX 1536
#define cH 3
#define NB (cB*cN)      // 8192
#define LISTCAP 64

// ---------------- scratch (static device globals; no allocations) ----------------
static __device__ float g_denom[NB];
static __device__ float g_ax[NB*cD];
static __device__ float g_t1[NB*cD];
static __device__ float g_t2[NB*cD];
static __device__ float g_out1[NB*cD];
static __device__ float g_conve[NB*cD];
static __device__ float g_wk[3*cN*cN];
static __device__ float g_x[NB*cX];
static __device__ float g_q[NB*cX];
static __device__ float g_k[NB*cX];
static __device__ float g_attn[(size_t)cB*cH*cN*cN];
static __device__ float g_rowsum[cB*cH*cN];
static __device__ float g_hsum[cB*cH];
static __device__ int   g_midx[cB];
static __device__ float g_cand[cB*32*2];
static __device__ float g_thr[cB];
static __device__ int   g_cnt[cB];
static __device__ int   g_list[cB*LISTCAP];
static __device__ int   g_nr[cB];
static __device__ int   g_ne[cB];
static __device__ int   g_rows[cB*LISTCAP];
static __device__ float g_dn2[cB*LISTCAP];
static __device__ int   g_eslot[cB*LISTCAP];
static __device__ int   g_ej[cB*LISTCAP];
static __device__ float g_eval[cB*LISTCAP];
static __device__ float g_ax2[cB*LISTCAP*cX];
static __device__ float g_out3[NB*cD];
static __device__ float g_hbuf[NB*cD];

// packed f32x2 FMA: two independent fp32 rn FMAs per issue (FFMA2).
typedef unsigned long long u64;
__device__ __forceinline__ u64 ffma2(u64 a, u64 b, u64 c) {
    u64 d;
    asm("fma.rn.f32x2 %0, %1, %2, %3;" : "=l"(d) : "l"(a), "l"(b), "l"(c));
    return d;
}

// smem layout (dynamic): As2[2][16][264] (A duplicated), Bs[2][16][132]
#define A_STRIDE 264
#define B_STRIDE 132
#define A_BUF (16*A_STRIDE)            // floats per A buffer
#define B_BUF (16*B_STRIDE)
#define SMEM_FLOATS (2*A_BUF + 2*B_BUF)
#define SMEM_SZ (SMEM_FLOATS*4)        // 50688 bytes

// ---------------- GEMM: C = alpha * A @ op(B) (+bias) (+C) (relu) ----------------
// BL==0: B is [N,K] row-major (C[m,n] = sum_k A[m,k]*B[n,k])  -- "NT"
// BL==1: B is [K,N] row-major (C[m,n] = sum_k A[m,k]*B[k,n])  -- "NN"
// Register-staged double buffering: LDG of tile t+1 overlaps compute of tile t.
template<int BL>
__global__ __launch_bounds__(256, 2)
void gemm_k(const float* __restrict__ A, const float* __restrict__ Bm,
            float* __restrict__ C,
            int M, int Nn, int K, int lda, int ldb, int ldc, int zmod,
            long long sA1, long long sA2, long long sB1, long long sB2,
            long long sC1, long long sC2,
            float alpha, const float* __restrict__ bias, int biasMode,
            int beta, int relu)
{
    extern __shared__ __align__(16) float smem_dyn[];
    float* AsBase = smem_dyn;                 // [2][16][A_STRIDE]
    float* BsBase = smem_dyn + 2 * A_BUF;     // [2][16][B_STRIDE]

    int z = blockIdx.z, z1 = z / zmod, z2 = z - z1 * zmod;
    A  += z1 * sA1 + z2 * sA2;
    Bm += z1 * sB1 + z2 * sB2;
    C  += z1 * sC1 + z2 * sC2;
    int bm = blockIdx.y * 128, bn = blockIdx.x * 128;
    int tid = threadIdx.x, tx = tid & 15, ty = tid >> 4;

    // staging-register tile load / store helpers (inlined logic)
    int ar = tid >> 1, akc = (tid & 1) * 8;       // A: row ar, k-chunk akc..akc+7
    float ra[8], rb[8];

    u64 acc[8][4];
    #pragma unroll
    for (int i = 0; i < 8; i++)
        #pragma unroll
        for (int j = 0; j < 4; j++) acc[i][j] = 0ull;

    // ---- prologue: load tile 0 into regs ----
    {
        int gm = bm + ar;
        #pragma unroll
        for (int i = 0; i < 8; i++) {
            int gk = akc + i;
            ra[i] = (gm < M && gk < K) ? A[(long long)gm * lda + gk] : 0.f;
        }
        if (BL == 0) {
            int gn = bn + ar;
            #pragma unroll
            for (int i = 0; i < 8; i++) {
                int gk = akc + i;
                rb[i] = (gn < Nn && gk < K) ? Bm[(long long)gn * ldb + gk] : 0.f;
            }
        } else {
            int kr = tid >> 4, nc = (tid & 15) * 8;
            int gk = kr;
            #pragma unroll
            for (int i = 0; i < 8; i++) {
                int gn = bn + nc + i;
                rb[i] = (gk < K && gn < Nn) ? Bm[(long long)gk * ldb + gn] : 0.f;
            }
        }
    }
    // ---- STS tile 0 into buffer 0 ----
    {
        #pragma unroll
        for (int i = 0; i < 8; i++) {
            AsBase[(akc + i) * A_STRIDE + 2 * ar]     = ra[i];
            AsBase[(akc + i) * A_STRIDE + 2 * ar + 1] = ra[i];
        }
        if (BL == 0) {
            #pragma unroll
            for (int i = 0; i < 8; i++)
                BsBase[(akc + i) * B_STRIDE + ar] = rb[i];
        } else {
            int kr = tid >> 4, nc = (tid & 15) * 8;
            #pragma unroll
            for (int i = 0; i < 8; i++)
                BsBase[kr * B_STRIDE + nc + i] = rb[i];
        }
    }
    __syncthreads();

    int cur = 0;
    for (int kb = 0; kb < K; kb += 16) {
        int kn = kb + 16;
        bool hasNext = kn < K;
        // ---- prefetch next tile into registers (latency overlaps compute) ----
        if (hasNext) {
            int gm = bm + ar;
            #pragma unroll
            for (int i = 0; i < 8; i++) {
                int gk = kn + akc + i;
                ra[i] = (gm < M && gk < K) ? A[(long long)gm * lda + gk] : 0.f;
            }
            if (BL == 0) {
                int gn = bn + ar;
                #pragma unroll
                for (int i = 0; i < 8; i++) {
                    int gk = kn + akc + i;
                    rb[i] = (gn < Nn && gk < K) ? Bm[(long long)gn * ldb + gk] : 0.f;
                }
            } else {
                int kr = tid >> 4, nc = (tid & 15) * 8;
                int gk = kn + kr;
                #pragma unroll
                for (int i = 0; i < 8; i++) {
                    int gn = bn + nc + i;
                    rb[i] = (gk < K && gn < Nn) ? Bm[(long long)gk * ldb + gn] : 0.f;
                }
            }
        }
        // ---- compute on buffer cur ----
        const float* As2 = AsBase + cur * A_BUF;
        const float* Bs  = BsBase + cur * B_BUF;
        #pragma unroll
        for (int k = 0; k < 16; k++) {
            ulonglong2 A0 = *(const ulonglong2*)&As2[k * A_STRIDE + ty * 8];
            ulonglong2 A1 = *(const ulonglong2*)&As2[k * A_STRIDE + ty * 8 + 4];
            ulonglong2 A2 = *(const ulonglong2*)&As2[k * A_STRIDE + 128 + ty * 8];
            ulonglong2 A3 = *(const ulonglong2*)&As2[k * A_STRIDE + 128 + ty * 8 + 4];
            ulonglong2 B0 = *(const ulonglong2*)&Bs[k * B_STRIDE + tx * 4];
            ulonglong2 B1 = *(const ulonglong2*)&Bs[k * B_STRIDE + 64 + tx * 4];
            u64 ad[8] = {A0.x, A0.y, A1.x, A1.y, A2.x, A2.y, A3.x, A3.y};
            u64 bp[4] = {B0.x, B0.y, B1.x, B1.y};
            #pragma unroll
            for (int i = 0; i < 8; i++)
                #pragma unroll
                for (int jp = 0; jp < 4; jp++)
                    acc[i][jp] = ffma2(ad[i], bp[jp], acc[i][jp]);
        }
        __syncthreads();
        // ---- STS next tile into alternate buffer ----
        if (hasNext) {
            float* Asn = AsBase + (1 - cur) * A_BUF;
            float* Bsn = BsBase + (1 - cur) * B_BUF;
            #pragma unroll
            for (int i = 0; i < 8; i++) {
                Asn[(akc + i) * A_STRIDE + 2 * ar]     = ra[i];
                Asn[(akc + i) * A_STRIDE + 2 * ar + 1] = ra[i];
            }
            if (BL == 0) {
                #pragma unroll
                for (int i = 0; i < 8; i++)
                    Bsn[(akc + i) * B_STRIDE + ar] = rb[i];
            } else {
                int kr = tid >> 4, nc = (tid & 15) * 8;
                #pragma unroll
                for (int i = 0; i < 8; i++)
                    Bsn[kr * B_STRIDE + nc + i] = rb[i];
            }
            __syncthreads();
            cur ^= 1;
        }
    }
    #pragma unroll
    for (int i = 0; i < 8; i++) {
        int gm = bm + ((i < 4) ? ty * 4 + i : 64 + ty * 4 + (i - 4));
        if (gm >= M) continue;
        #pragma unroll
        for (int jp = 0; jp < 4; jp++) {
            #pragma unroll
            for (int h = 0; h < 2; h++) {
                int gn = bn + ((jp < 2) ? tx * 4 + jp * 2 + h
                                        : 64 + tx * 4 + (jp - 2) * 2 + h);
                if (gn >= Nn) continue;
                unsigned int bits = h ? (unsigned int)(acc[i][jp] >> 32)
                                      : (unsigned int)(acc[i][jp] & 0xFFFFFFFFu);
                float v = __uint_as_float(bits);
                v *= alpha;
                if (bias) v += biasMode ? bias[gm] : bias[gn];
                long long o = (long long)gm * ldc + gn;
                if (beta) v += C[o];
                if (relu) v = fmaxf(v, 0.f);
                C[o] = v;
            }
        }
    }
}

// ---------------- small kernels ----------------
__global__ void denom_kernel(const float* __restrict__ adj) {
    int row = blockIdx.x;
    const float* a = adj + (size_t)row * cN;
    int t = threadIdx.x;
    __shared__ float red[256];
    red[t] = (a[t] + a[t + 256]) + (a[t + 512] + a[t + 768]);
    __syncthreads();
    for (int k = 128; k > 0; k >>= 1) { if (t < k) red[t] += red[t + k]; __syncthreads(); }
    if (t == 0) g_denom[row] = red[0] + 1.f;
}

__global__ void combine1_kernel() {
    int idx = blockIdx.x * 256 + threadIdx.x;
    float d = g_denom[idx / cD];
    g_out1[idx] = fmaxf(g_t1[idx] / d, 0.f) + g_t2[idx];
}

__global__ void repack_kernel(const float* __restrict__ w) {
    int idx = blockIdx.x * 256 + threadIdx.x;   // o*1024+i, < 1048576
    #pragma unroll
    for (int kk = 0; kk < 3; kk++)
        g_wk[kk * (cN * cN) + idx] = w[(size_t)idx * 3 + kk];
}

__global__ void copyx_kernel(const float* __restrict__ inp) {
    int idx = blockIdx.x * 256 + threadIdx.x;   // over NB*cD
    int r = idx / cD, d = idx - r * cD;
    g_x[(size_t)r * cX + d] = inp[idx];
}

__global__ void softmax_kernel() {
    float* p = g_attn + (size_t)blockIdx.x * cN;
    int t = threadIdx.x;
    __shared__ float red[256];
    float v0 = p[t], v1 = p[t + 256], v2 = p[t + 512], v3 = p[t + 768];
    red[t] = fmaxf(fmaxf(v0, v1), fmaxf(v2, v3));
    __syncthreads();
    for (int k = 128; k > 0; k >>= 1) { if (t < k) red[t] = fmaxf(red[t], red[t + k]); __syncthreads(); }
    float m = red[0]; __syncthreads();
    v0 = expf(v0 - m); v1 = expf(v1 - m); v2 = expf(v2 - m); v3 = expf(v3 - m);
    red[t] = (v0 + v1) + (v2 + v3); __syncthreads();
    for (int k = 128; k > 0; k >>= 1) { if (t < k) red[t] += red[t + k]; __syncthreads(); }
    float Z = red[0]; __syncthreads();
    v0 /= Z; v1 /= Z; v2 /= Z; v3 /= Z;
    p[t] = v0; p[t + 256] = v1; p[t + 512] = v2; p[t + 768] = v3;
    red[t] = (v0 + v1) + (v2 + v3); __syncthreads();
    for (int k = 128; k > 0; k >>= 1) { if (t < k) red[t] += red[t + k]; __syncthreads(); }
    if (t == 0) g_rowsum[blockIdx.x] = red[0];
}

__global__ void headsum_kernel() {
    int bh = blockIdx.x, t = threadIdx.x;
    const float* r = g_rowsum + bh * cN;
    __shared__ float red[256];
    red[t] = (r[t] + r[t + 256]) + (r[t + 512] + r[t + 768]);
    __syncthreads();
    for (int k = 128; k > 0; k >>= 1) { if (t < k) red[t] += red[t + k]; __syncthreads(); }
    if (t == 0) g_hsum[bh] = red[0];
}

__global__ void choose_kernel() {
    if (threadIdx.x || blockIdx.x) return;
    float pr[cB][cH];
    for (int h = 0; h < cH; h++) {
        float M = -3.4e38f;
        for (int b = 0; b < cB; b++) M = fmaxf(M, g_hsum[b * cH + h]);
        float Dn = 0.f;
        for (int b = 0; b < cB; b++) Dn += expf(g_hsum[b * cH + h] - M);
        for (int b = 0; b < cB; b++) pr[b][h] = expf(g_hsum[b * cH + h] - M) / Dn;
    }
    for (int b = 0; b < cB; b++) {
        int mi = 0;
        if (pr[b][1] > pr[b][mi]) mi = 1;
        if (pr[b][2] > pr[b][mi]) mi = 2;
        g_midx[b] = mi;   // first-max-wins, matches jnp.argmax
    }
}

__device__ __forceinline__ void t2merge(float& m1, float& m2, float b1, float b2) {
    if (b1 > m1) { m2 = fmaxf(m1, b2); m1 = b1; } else { m2 = fmaxf(m2, b1); }
}

__global__ void top2a_kernel() {
    int bx = blockIdx.x; int b = bx >> 5, c = bx & 31;
    const float* p = g_attn + (size_t)(b * cH + g_midx[b]) * (size_t)(cN * cN)
                            + (size_t)c * 32768;
    float m1 = -3.4e38f, m2 = -3.4e38f;
    for (int i = threadIdx.x; i < 32768; i += 256) {
        float v = p[i];
        if (v > m1) { m2 = m1; m1 = v; } else if (v > m2) m2 = v;
    }
    __shared__ float s1[256], s2[256];
    int t = threadIdx.x;
    s1[t] = m1; s2[t] = m2; __syncthreads();
    for (int k = 128; k > 0; k >>= 1) {
        if (t < k) t2merge(s1[t], s2[t], s1[t + k], s2[t + k]);
        __syncthreads();
    }
    if (t == 0) { g_cand[bx * 2] = s1[0]; g_cand[bx * 2 + 1] = s2[0]; }
}

__global__ void top2b_kernel() {
    int b = blockIdx.x;
    if (threadIdx.x == 0) {
        float m1 = -3.4e38f, m2 = -3.4e38f;
        for (int c = 0; c < 32; c++)
            t2merge(m1, m2, g_cand[(b * 32 + c) * 2], g_cand[(b * 32 + c) * 2 + 1]);
        g_thr[b] = m2;   // 2nd-largest with multiplicity == top_k(flat,2)[..,-1]
        g_cnt[b] = 0;
    }
}

__global__ void build_kernel() {
    int bx = blockIdx.x; int b = bx >> 5, c = bx & 31;
    const float* p = g_attn + (size_t)(b * cH + g_midx[b]) * (size_t)(cN * cN);
    size_t base = (size_t)c * 32768;
    float thr = g_thr[b];
    for (int i = threadIdx.x; i < 32768; i += 256) {
        if (p[base + i] >= thr) {
            int pos = atomicAdd(&g_cnt[b], 1);
            if (pos < LISTCAP) g_list[b * LISTCAP + pos] = (int)(base + i);
        }
    }
}

__global__ void process_kernel() {
    int b = blockIdx.x;
    if (threadIdx.x) return;
    int n = g_cnt[b]; if (n > LISTCAP) n = LISTCAP;
    int* L = &g_list[b * LISTCAP];
    for (int i = 1; i < n; i++) {           // deterministic order
        int key = L[i], j = i - 1;
        while (j >= 0 && L[j] > key) { L[j + 1] = L[j]; j--; }
        L[j + 1] = key;
    }
    int nr = 0, ne = 0;
    for (int e = 0; e < n; e++) {
        int code = L[e], i = code >> 10, j = code & 1023;
        float val;
        if (i == j) val = 1.f;
        else {
            int rc = (j << 10) | i; bool f = false;
            for (int q2 = 0; q2 < n; q2++) if (L[q2] == rc) { f = true; break; }
            val = f ? 2.f : 1.f;            // (binm + binm^T, diag->1) * binm
        }
        int slot = -1;
        for (int r = 0; r < nr; r++) if (g_rows[b * LISTCAP + r] == i) { slot = r; break; }
        if (slot < 0) {
            slot = nr; g_rows[b * LISTCAP + nr] = i; g_dn2[b * LISTCAP + nr] = 1.f; nr++;
        }
        g_dn2[b * LISTCAP + slot] += val;   // denom2 = rowsum + 1
        g_eslot[b * LISTCAP + ne] = slot;
        g_ej[b * LISTCAP + ne] = j;
        g_eval[b * LISTCAP + ne] = val;
        ne++;
    }
    g_nr[b] = nr; g_ne[b] = ne;
}

__global__ void sparse_ax_kernel() {
    int bid = blockIdx.x; int b = bid / LISTCAP, slot = bid - b * LISTCAP;
    if (slot >= g_nr[b]) return;
    int ne = g_ne[b];
    for (int c = threadIdx.x; c < cX; c += 256) {
        float acc = 0.f;
        for (int e = 0; e < ne; e++) {
            if (g_eslot[b * LISTCAP + e] == slot) {
                int j = g_ej[b * LISTCAP + e];
                acc += g_eval[b * LISTCAP + e] * g_x[(size_t)(b * cN + j) * cX + c];
            }
        }
        g_ax2[(size_t)bid * cX + c] = acc;
    }
}

__global__ void sparse_fix_kernel(const float* __restrict__ W1w,
                                  const float* __restrict__ W1b) {
    int bid = blockIdx.x; int b = bid / LISTCAP, slot = bid - b * LISTCAP;
    if (slot >= g_nr[b]) return;
    int row = g_rows[b * LISTCAP + slot];
    float dn = g_dn2[b * LISTCAP + slot];
    const float* ax = &g_ax2[(size_t)bid * cX];
    #pragma unroll
    for (int dd = 0; dd < 3; dd++) {
        int d = threadIdx.x + dd * 256;
        const float* w = W1w + (size_t)d * cX;
        float y = 0.f;
        for (int c = 0; c < cX; c++) y += ax[c] * w[c];
        float v = fmaxf((y + W1b[d]) / dn, 0.f);
        g_out3[(size_t)(b * cN + row) * cD + d] += v;
    }
}

// ---------------- host side ----------------
static void run_gemm(int BL, dim3 grid, const float* A, const float* Bm, float* C,
                     int M, int Nn, int K, int lda, int ldb, int ldc, int zmod,
                     long long sA1, long long sA2, long long sB1, long long sB2,
                     long long sC1, long long sC2,
                     float alpha, const float* bias, int biasMode, int beta, int relu)
{
    if (BL == 0)
        gemm_k<0><<<grid, 256, SMEM_SZ>>>(A, Bm, C, M, Nn, K, lda, ldb, ldc, zmod,
                                 sA1, sA2, sB1, sB2, sC1, sC2, alpha, bias, biasMode, beta, relu);
    else
        gemm_k<1><<<grid, 256, SMEM_SZ>>>(A, Bm, C, M, Nn, K, lda, ldb, ldc, zmod,
                                 sA1, sA2, sB1, sB2, sC1, sC2, alpha, bias, biasMode, beta, relu);
}

#define GS(p, sym) do { void* _t = 0; cudaGetSymbolAddress(&_t, sym); p = (float*)_t; } while (0)

extern "C" void kernel_launch(void* const* d_in, const int* in_sizes, int n_in,
                              void* d_out, int out_size)
{
    const float* adj      = (const float*)d_in[0];
    const float* inputs   = (const float*)d_in[1];
    const float* W0_w     = (const float*)d_in[3];
    const float* W0_b     = (const float*)d_in[4];
    const float* W1_w     = (const float*)d_in[5];
    const float* W1_b     = (const float*)d_in[6];
    const float* linc_w   = (const float*)d_in[7];
    const float* linc_b   = (const float*)d_in[8];
    const float* fc1_w    = (const float*)d_in[9];
    const float* fc2_w    = (const float*)d_in[10];
    const float* conv_w   = (const float*)d_in[11];
    const float* conv_b   = (const float*)d_in[12];
    const float* aq_w     = (const float*)d_in[13];
    const float* aq_b     = (const float*)d_in[14];
    const float* ak_w     = (const float*)d_in[15];
    const float* ak_b     = (const float*)d_in[16];
    float* out = (float*)d_out;

    // opt-in >48KB dynamic smem (not an allocation; idempotent; capture-safe)
    cudaFuncSetAttribute((const void*)gemm_k<0>, cudaFuncAttributeMaxDynamicSharedMemorySize, SMEM_SZ);
    cudaFuncSetAttribute((const void*)gemm_k<1>, cudaFuncAttributeMaxDynamicSharedMemorySize, SMEM_SZ);

    float *pax, *pt1, *pt2, *pout1, *pconve, *pwk, *px, *pq, *pk, *pattn, *pout3, *phbuf;
    GS(pax, g_ax); GS(pt1, g_t1); GS(pt2, g_t2); GS(pout1, g_out1);
    GS(pconve, g_conve); GS(pwk, g_wk); GS(px, g_x); GS(pq, g_q); GS(pk, g_k);
    GS(pattn, g_attn); GS(pout3, g_out3); GS(phbuf, g_hbuf);

    const long long sND = (long long)cN * cD;        // 786432
    const long long sNX = (long long)cN * cX;
    const long long sNN = (long long)cN * cN;

    // 1) denom = adj.sum(2) + 1
    denom_kernel<<<NB, 256>>>(adj);

    // 2) Ax = adj @ inputs  (8 batches, NN layout)
    run_gemm(1, dim3(cD/128, cN/128, cB), adj, inputs, pax,
             cN, cD, cN, cN, cD, cD, 1, sNN, 0, sND, 0, sND, 0,
             1.f, 0, 0, 0, 0);

    // 3) t1 = Ax @ W0^T + b ; 4) t2 = inputs @ W0^T + b
    run_gemm(0, dim3(cD/128, NB/128, 1), pax, W0_w, pt1,
             NB, cD, cD, cD, cD, cD, 1, 0,0,0,0,0,0, 1.f, W0_b, 0, 0, 0);
    run_gemm(0, dim3(cD/128, NB/128, 1), inputs, W0_w, pt2,
             NB, cD, cD, cD, cD, cD, 1, 0,0,0,0,0,0, 1.f, W0_b, 0, 0, 0);

    // 5) out1 = relu(t1/denom) + t2
    combine1_kernel<<<NB*cD/256, 256>>>();

    // 6) conv: repack weights, 3 accumulated GEMMs (bias on k=0, relu on k=2)
    repack_kernel<<<(cN*cN)/256, 256>>>(conv_w);
    for (int kk = 0; kk < 3; kk++)
        run_gemm(1, dim3(6, cN/128, cB), pwk + (long long)kk*cN*cN, pout1 + kk, pconve,
                 cN, cD-2, cN, cN, cD, cD, 1, 0, 0, sND, 0, sND, 0,
                 1.f, (kk==0) ? conv_b : 0, 1, (kk>0), (kk==2));

    // 7) x = concat([inputs, linearc(conve)], -1)
    copyx_kernel<<<NB*cD/256, 256>>>(inputs);
    run_gemm(0, dim3(cD/128, NB/128, 1), pconve, linc_w, px + cD,
             NB, cD, cD-2, cD, cD-2, cX, 1, 0,0,0,0,0,0, 1.f, linc_b, 0, 0, 0);

    // 8) q, k projections
    run_gemm(0, dim3(cX/128, NB/128, 1), px, aq_w, pq,
             NB, cX, cX, cX, cX, cX, 1, 0,0,0,0,0,0, 1.f, aq_b, 0, 0, 0);
    run_gemm(0, dim3(cX/128, NB/128, 1), px, ak_w, pk,
             NB, cX, cX, cX, cX, cX, 1, 0,0,0,0,0,0, 1.f, ak_b, 0, 0, 0);

    // 9) scores: 24 (b,h) GEMMs in one launch, z = b*3+h
    run_gemm(0, dim3(cN/128, cN/128, cB*cH), pq, pk, pattn,
             cN, cN, 512, cX, cX, cN, cH,
             sNX, 512, sNX, 512, (long long)cH*sNN, sNN,
             0.044194173824159216f, 0, 0, 0, 0);

    // 10) softmax rows + rowsums + head sums + head choice
    softmax_kernel<<<cB*cH*cN, 256>>>();
    headsum_kernel<<<cB*cH, 256>>>();
    choose_kernel<<<1, 32>>>();

    // 11) global top-2 threshold + sparse adj2 edge list
    top2a_kernel<<<cB*32, 256>>>();
    top2b_kernel<<<cB, 32>>>();
    build_kernel<<<cB*32, 256>>>();
    process_kernel<<<cB, 32>>>();

    // 12) dense part of GCN layer 2: out3 = x @ W1^T + b
    run_gemm(0, dim3(cD/128, NB/128, 1), px, W1_w, pout3,
             NB, cD, cX, cX, cX, cD, 1, 0,0,0,0,0,0, 1.f, W1_b, 0, 0, 0);

    // 13) sparse correction: out3[row] += relu((adj2@x @ W1^T + b)/denom2)
    sparse_ax_kernel<<<cB*LISTCAP, 256>>>();
    sparse_fix_kernel<<<cB*LISTCAP, 256>>>(W1_w, W1_b);

    // 14) fc: out = fc2( relu(fc1(out3)) )
    run_gemm(0, dim3(cD/128, NB/128, 1), pout3, fc1_w, phbuf,
             NB, cD, cD, cD, cD, cD, 1, 0,0,0,0,0,0, 1.f, 0, 0, 0, 1);
    run_gemm(0, dim3(cD/128, NB/128, 1), phbuf, fc2_w, out,
             NB, cD, cD, cD, cD, cD, 1, 0,0,0,0,0,0, 1.f, 0, 0, 0, 0);
}

// round 11
// speedup vs baseline: 1.2613x; 1.2313x over previous
#include <cuda_runtime.h>
#include <math.h>

#define cB 8
#define cN 1024
#define cD 768
#define cX 1536
#define cH 3
#define NB (cB*cN)      // 8192
#define LISTCAP 64

// ---------------- scratch (static device globals; no allocations) ----------------
static __device__ float g_denom[NB];
static __device__ float g_ax[NB*cD];
static __device__ float g_t1[NB*cD];
static __device__ float g_t2[NB*cD];
static __device__ float g_out1[NB*cD];
static __device__ float g_conve[NB*cD];
static __device__ float g_wk[3*cN*cN];
static __device__ float g_x[NB*cX];
static __device__ float g_q[NB*cX];
static __device__ float g_k[NB*cX];
static __device__ float g_attn[(size_t)cB*cH*cN*cN];
static __device__ float g_rowsum[cB*cH*cN];
static __device__ float g_hsum[cB*cH];
static __device__ int   g_midx[cB];
static __device__ float g_cand[cB*32*2];
static __device__ float g_thr[cB];
static __device__ int   g_cnt[cB];
static __device__ int   g_list[cB*LISTCAP];
static __device__ int   g_nr[cB];
static __device__ int   g_ne[cB];
static __device__ int   g_rows[cB*LISTCAP];
static __device__ float g_dn2[cB*LISTCAP];
static __device__ int   g_eslot[cB*LISTCAP];
static __device__ int   g_ej[cB*LISTCAP];
static __device__ float g_eval[cB*LISTCAP];
static __device__ float g_ax2[cB*LISTCAP*cX];
static __device__ float g_out3[NB*cD];
static __device__ float g_hbuf[NB*cD];

// packed f32x2 FMA: two independent fp32 rn FMAs per issue (FFMA2).
typedef unsigned long long u64;
__device__ __forceinline__ u64 ffma2(u64 a, u64 b, u64 c) {
    u64 d;
    asm("fma.rn.f32x2 %0, %1, %2, %3;" : "=l"(d) : "l"(a), "l"(b), "l"(c));
    return d;
}
// duplicate one fp32 into both halves of a packed pair (ALU pipe, not FMA)
__device__ __forceinline__ u64 dup2(float v) {
    u64 d;
    asm("mov.b64 %0, {%1, %1};" : "=l"(d) : "f"(v));
    return d;
}

#define TS 132   // smem row stride (floats) for both A and B tiles

// ---------------- GEMM: C = alpha * A @ op(B) (+bias) (+C) (relu) ----------------
// BL==0: B is [N,K] row-major (C[m,n] = sum_k A[m,k]*B[n,k])  -- "NT"
// BL==1: B is [K,N] row-major (C[m,n] = sum_k A[m,k]*B[k,n])  -- "NN"
// Register-staged double buffering; A stored non-duplicated (dup happens in regs).
template<int BL>
__global__ __launch_bounds__(256, 2)
void gemm_k(const float* __restrict__ A, const float* __restrict__ Bm,
            float* __restrict__ C,
            int M, int Nn, int K, int lda, int ldb, int ldc, int zmod,
            long long sA1, long long sA2, long long sB1, long long sB2,
            long long sC1, long long sC2,
            float alpha, const float* __restrict__ bias, int biasMode,
            int beta, int relu)
{
    __shared__ __align__(16) float As[2][16][TS];
    __shared__ __align__(16) float Bs[2][16][TS];

    int z = blockIdx.z, z1 = z / zmod, z2 = z - z1 * zmod;
    A  += z1 * sA1 + z2 * sA2;
    Bm += z1 * sB1 + z2 * sB2;
    C  += z1 * sC1 + z2 * sC2;
    int bm = blockIdx.y * 128, bn = blockIdx.x * 128;
    int tid = threadIdx.x, tx = tid & 15, ty = tid >> 4;

    int ar = tid >> 1, akc = (tid & 1) * 8;       // A/B(NT): row ar, k-chunk akc..akc+7
    float ra[8], rb[8];

    u64 acc[8][4];
    #pragma unroll
    for (int i = 0; i < 8; i++)
        #pragma unroll
        for (int j = 0; j < 4; j++) acc[i][j] = 0ull;

    // ---- prologue: load tile 0 into regs ----
    {
        int gm = bm + ar;
        #pragma unroll
        for (int i = 0; i < 8; i++) {
            int gk = akc + i;
            ra[i] = (gm < M && gk < K) ? A[(long long)gm * lda + gk] : 0.f;
        }
        if (BL == 0) {
            int gn = bn + ar;
            #pragma unroll
            for (int i = 0; i < 8; i++) {
                int gk = akc + i;
                rb[i] = (gn < Nn && gk < K) ? Bm[(long long)gn * ldb + gk] : 0.f;
            }
        } else {
            int kr = tid >> 4, nc = (tid & 15) * 8;
            int gk = kr;
            #pragma unroll
            for (int i = 0; i < 8; i++) {
                int gn = bn + nc + i;
                rb[i] = (gk < K && gn < Nn) ? Bm[(long long)gk * ldb + gn] : 0.f;
            }
        }
    }
    // ---- STS tile 0 into buffer 0 ----
    {
        #pragma unroll
        for (int i = 0; i < 8; i++)
            As[0][akc + i][ar] = ra[i];
        if (BL == 0) {
            #pragma unroll
            for (int i = 0; i < 8; i++)
                Bs[0][akc + i][ar] = rb[i];
        } else {
            int kr = tid >> 4, nc = (tid & 15) * 8;
            #pragma unroll
            for (int i = 0; i < 8; i++)
                Bs[0][kr][nc + i] = rb[i];
        }
    }
    __syncthreads();

    int cur = 0;
    for (int kb = 0; kb < K; kb += 16) {
        int kn = kb + 16;
        bool hasNext = kn < K;
        // ---- prefetch next tile into registers (latency overlaps compute) ----
        if (hasNext) {
            int gm = bm + ar;
            #pragma unroll
            for (int i = 0; i < 8; i++) {
                int gk = kn + akc + i;
                ra[i] = (gm < M && gk < K) ? A[(long long)gm * lda + gk] : 0.f;
            }
            if (BL == 0) {
                int gn = bn + ar;
                #pragma unroll
                for (int i = 0; i < 8; i++) {
                    int gk = kn + akc + i;
                    rb[i] = (gn < Nn && gk < K) ? Bm[(long long)gn * ldb + gk] : 0.f;
                }
            } else {
                int kr = tid >> 4, nc = (tid & 15) * 8;
                int gk = kn + kr;
                #pragma unroll
                for (int i = 0; i < 8; i++) {
                    int gn = bn + nc + i;
                    rb[i] = (gk < K && gn < Nn) ? Bm[(long long)gk * ldb + gn] : 0.f;
                }
            }
        }
        // ---- compute on buffer cur ----
        #pragma unroll
        for (int k = 0; k < 16; k++) {
            float4 a0 = *(const float4*)&As[cur][k][ty * 4];
            float4 a1 = *(const float4*)&As[cur][k][64 + ty * 4];
            ulonglong2 B0 = *(const ulonglong2*)&Bs[cur][k][tx * 4];
            ulonglong2 B1 = *(const ulonglong2*)&Bs[cur][k][64 + tx * 4];
            u64 ad[8] = {dup2(a0.x), dup2(a0.y), dup2(a0.z), dup2(a0.w),
                         dup2(a1.x), dup2(a1.y), dup2(a1.z), dup2(a1.w)};
            u64 bp[4] = {B0.x, B0.y, B1.x, B1.y};
            #pragma unroll
            for (int i = 0; i < 8; i++)
                #pragma unroll
                for (int jp = 0; jp < 4; jp++)
                    acc[i][jp] = ffma2(ad[i], bp[jp], acc[i][jp]);
        }
        __syncthreads();
        // ---- STS next tile into alternate buffer ----
        if (hasNext) {
            int nxt = 1 - cur;
            #pragma unroll
            for (int i = 0; i < 8; i++)
                As[nxt][akc + i][ar] = ra[i];
            if (BL == 0) {
                #pragma unroll
                for (int i = 0; i < 8; i++)
                    Bs[nxt][akc + i][ar] = rb[i];
            } else {
                int kr = tid >> 4, nc = (tid & 15) * 8;
                #pragma unroll
                for (int i = 0; i < 8; i++)
                    Bs[nxt][kr][nc + i] = rb[i];
            }
            __syncthreads();
            cur = nxt;
        }
    }
    #pragma unroll
    for (int i = 0; i < 8; i++) {
        int gm = bm + ((i < 4) ? ty * 4 + i : 64 + ty * 4 + (i - 4));
        if (gm >= M) continue;
        #pragma unroll
        for (int jp = 0; jp < 4; jp++) {
            #pragma unroll
            for (int h = 0; h < 2; h++) {
                int gn = bn + ((jp < 2) ? tx * 4 + jp * 2 + h
                                        : 64 + tx * 4 + (jp - 2) * 2 + h);
                if (gn >= Nn) continue;
                unsigned int bits = h ? (unsigned int)(acc[i][jp] >> 32)
                                      : (unsigned int)(acc[i][jp] & 0xFFFFFFFFu);
                float v = __uint_as_float(bits);
                v *= alpha;
                if (bias) v += biasMode ? bias[gm] : bias[gn];
                long long o = (long long)gm * ldc + gn;
                if (beta) v += C[o];
                if (relu) v = fmaxf(v, 0.f);
                C[o] = v;
            }
        }
    }
}

// ---------------- small kernels ----------------
__global__ void denom_kernel(const float* __restrict__ adj) {
    int row = blockIdx.x;
    const float* a = adj + (size_t)row * cN;
    int t = threadIdx.x;
    __shared__ float red[256];
    red[t] = (a[t] + a[t + 256]) + (a[t + 512] + a[t + 768]);
    __syncthreads();
    for (int k = 128; k > 0; k >>= 1) { if (t < k) red[t] += red[t + k]; __syncthreads(); }
    if (t == 0) g_denom[row] = red[0] + 1.f;
}

__global__ void combine1_kernel() {
    int idx = blockIdx.x * 256 + threadIdx.x;
    float d = g_denom[idx / cD];
    g_out1[idx] = fmaxf(g_t1[idx] / d, 0.f) + g_t2[idx];
}

__global__ void repack_kernel(const float* __restrict__ w) {
    int idx = blockIdx.x * 256 + threadIdx.x;   // o*1024+i, < 1048576
    #pragma unroll
    for (int kk = 0; kk < 3; kk++)
        g_wk[kk * (cN * cN) + idx] = w[(size_t)idx * 3 + kk];
}

__global__ void copyx_kernel(const float* __restrict__ inp) {
    int idx = blockIdx.x * 256 + threadIdx.x;   // over NB*cD
    int r = idx / cD, d = idx - r * cD;
    g_x[(size_t)r * cX + d] = inp[idx];
}

__global__ void softmax_kernel() {
    float* p = g_attn + (size_t)blockIdx.x * cN;
    int t = threadIdx.x;
    __shared__ float red[256];
    float v0 = p[t], v1 = p[t + 256], v2 = p[t + 512], v3 = p[t + 768];
    red[t] = fmaxf(fmaxf(v0, v1), fmaxf(v2, v3));
    __syncthreads();
    for (int k = 128; k > 0; k >>= 1) { if (t < k) red[t] = fmaxf(red[t], red[t + k]); __syncthreads(); }
    float m = red[0]; __syncthreads();
    v0 = expf(v0 - m); v1 = expf(v1 - m); v2 = expf(v2 - m); v3 = expf(v3 - m);
    red[t] = (v0 + v1) + (v2 + v3); __syncthreads();
    for (int k = 128; k > 0; k >>= 1) { if (t < k) red[t] += red[t + k]; __syncthreads(); }
    float Z = red[0]; __syncthreads();
    v0 /= Z; v1 /= Z; v2 /= Z; v3 /= Z;
    p[t] = v0; p[t + 256] = v1; p[t + 512] = v2; p[t + 768] = v3;
    red[t] = (v0 + v1) + (v2 + v3); __syncthreads();
    for (int k = 128; k > 0; k >>= 1) { if (t < k) red[t] += red[t + k]; __syncthreads(); }
    if (t == 0) g_rowsum[blockIdx.x] = red[0];
}

__global__ void headsum_kernel() {
    int bh = blockIdx.x, t = threadIdx.x;
    const float* r = g_rowsum + bh * cN;
    __shared__ float red[256];
    red[t] = (r[t] + r[t + 256]) + (r[t + 512] + r[t + 768]);
    __syncthreads();
    for (int k = 128; k > 0; k >>= 1) { if (t < k) red[t] += red[t + k]; __syncthreads(); }
    if (t == 0) g_hsum[bh] = red[0];
}

__global__ void choose_kernel() {
    if (threadIdx.x || blockIdx.x) return;
    float pr[cB][cH];
    for (int h = 0; h < cH; h++) {
        float M = -3.4e38f;
        for (int b = 0; b < cB; b++) M = fmaxf(M, g_hsum[b * cH + h]);
        float Dn = 0.f;
        for (int b = 0; b < cB; b++) Dn += expf(g_hsum[b * cH + h] - M);
        for (int b = 0; b < cB; b++) pr[b][h] = expf(g_hsum[b * cH + h] - M) / Dn;
    }
    for (int b = 0; b < cB; b++) {
        int mi = 0;
        if (pr[b][1] > pr[b][mi]) mi = 1;
        if (pr[b][2] > pr[b][mi]) mi = 2;
        g_midx[b] = mi;   // first-max-wins, matches jnp.argmax
    }
}

__device__ __forceinline__ void t2merge(float& m1, float& m2, float b1, float b2) {
    if (b1 > m1) { m2 = fmaxf(m1, b2); m1 = b1; } else { m2 = fmaxf(m2, b1); }
}

__global__ void top2a_kernel() {
    int bx = blockIdx.x; int b = bx >> 5, c = bx & 31;
    const float* p = g_attn + (size_t)(b * cH + g_midx[b]) * (size_t)(cN * cN)
                            + (size_t)c * 32768;
    float m1 = -3.4e38f, m2 = -3.4e38f;
    for (int i = threadIdx.x; i < 32768; i += 256) {
        float v = p[i];
        if (v > m1) { m2 = m1; m1 = v; } else if (v > m2) m2 = v;
    }
    __shared__ float s1[256], s2[256];
    int t = threadIdx.x;
    s1[t] = m1; s2[t] = m2; __syncthreads();
    for (int k = 128; k > 0; k >>= 1) {
        if (t < k) t2merge(s1[t], s2[t], s1[t + k], s2[t + k]);
        __syncthreads();
    }
    if (t == 0) { g_cand[bx * 2] = s1[0]; g_cand[bx * 2 + 1] = s2[0]; }
}

__global__ void top2b_kernel() {
    int b = blockIdx.x;
    if (threadIdx.x == 0) {
        float m1 = -3.4e38f, m2 = -3.4e38f;
        for (int c = 0; c < 32; c++)
            t2merge(m1, m2, g_cand[(b * 32 + c) * 2], g_cand[(b * 32 + c) * 2 + 1]);
        g_thr[b] = m2;   // 2nd-largest with multiplicity == top_k(flat,2)[..,-1]
        g_cnt[b] = 0;
    }
}

__global__ void build_kernel() {
    int bx = blockIdx.x; int b = bx >> 5, c = bx & 31;
    const float* p = g_attn + (size_t)(b * cH + g_midx[b]) * (size_t)(cN * cN);
    size_t base = (size_t)c * 32768;
    float thr = g_thr[b];
    for (int i = threadIdx.x; i < 32768; i += 256) {
        if (p[base + i] >= thr) {
            int pos = atomicAdd(&g_cnt[b], 1);
            if (pos < LISTCAP) g_list[b * LISTCAP + pos] = (int)(base + i);
        }
    }
}

__global__ void process_kernel() {
    int b = blockIdx.x;
    if (threadIdx.x) return;
    int n = g_cnt[b]; if (n > LISTCAP) n = LISTCAP;
    int* L = &g_list[b * LISTCAP];
    for (int i = 1; i < n; i++) {           // deterministic order
        int key = L[i], j = i - 1;
        while (j >= 0 && L[j] > key) { L[j + 1] = L[j]; j--; }
        L[j + 1] = key;
    }
    int nr = 0, ne = 0;
    for (int e = 0; e < n; e++) {
        int code = L[e], i = code >> 10, j = code & 1023;
        float val;
        if (i == j) val = 1.f;
        else {
            int rc = (j << 10) | i; bool f = false;
            for (int q2 = 0; q2 < n; q2++) if (L[q2] == rc) { f = true; break; }
            val = f ? 2.f : 1.f;            // (binm + binm^T, diag->1) * binm
        }
        int slot = -1;
        for (int r = 0; r < nr; r++) if (g_rows[b * LISTCAP + r] == i) { slot = r; break; }
        if (slot < 0) {
            slot = nr; g_rows[b * LISTCAP + nr] = i; g_dn2[b * LISTCAP + nr] = 1.f; nr++;
        }
        g_dn2[b * LISTCAP + slot] += val;   // denom2 = rowsum + 1
        g_eslot[b * LISTCAP + ne] = slot;
        g_ej[b * LISTCAP + ne] = j;
        g_eval[b * LISTCAP + ne] = val;
        ne++;
    }
    g_nr[b] = nr; g_ne[b] = ne;
}

__global__ void sparse_ax_kernel() {
    int bid = blockIdx.x; int b = bid / LISTCAP, slot = bid - b * LISTCAP;
    if (slot >= g_nr[b]) return;
    int ne = g_ne[b];
    for (int c = threadIdx.x; c < cX; c += 256) {
        float acc = 0.f;
        for (int e = 0; e < ne; e++) {
            if (g_eslot[b * LISTCAP + e] == slot) {
                int j = g_ej[b * LISTCAP + e];
                acc += g_eval[b * LISTCAP + e] * g_x[(size_t)(b * cN + j) * cX + c];
            }
        }
        g_ax2[(size_t)bid * cX + c] = acc;
    }
}

__global__ void sparse_fix_kernel(const float* __restrict__ W1w,
                                  const float* __restrict__ W1b) {
    int bid = blockIdx.x; int b = bid / LISTCAP, slot = bid - b * LISTCAP;
    if (slot >= g_nr[b]) return;
    int row = g_rows[b * LISTCAP + slot];
    float dn = g_dn2[b * LISTCAP + slot];
    const float* ax = &g_ax2[(size_t)bid * cX];
    #pragma unroll
    for (int dd = 0; dd < 3; dd++) {
        int d = threadIdx.x + dd * 256;
        const float* w = W1w + (size_t)d * cX;
        float y = 0.f;
        for (int c = 0; c < cX; c++) y += ax[c] * w[c];
        float v = fmaxf((y + W1b[d]) / dn, 0.f);
        g_out3[(size_t)(b * cN + row) * cD + d] += v;
    }
}

// ---------------- host side ----------------
static void run_gemm(int BL, dim3 grid, const float* A, const float* Bm, float* C,
                     int M, int Nn, int K, int lda, int ldb, int ldc, int zmod,
                     long long sA1, long long sA2, long long sB1, long long sB2,
                     long long sC1, long long sC2,
                     float alpha, const float* bias, int biasMode, int beta, int relu)
{
    if (BL == 0)
        gemm_k<0><<<grid, 256>>>(A, Bm, C, M, Nn, K, lda, ldb, ldc, zmod,
                                 sA1, sA2, sB1, sB2, sC1, sC2, alpha, bias, biasMode, beta, relu);
    else
        gemm_k<1><<<grid, 256>>>(A, Bm, C, M, Nn, K, lda, ldb, ldc, zmod,
                                 sA1, sA2, sB1, sB2, sC1, sC2, alpha, bias, biasMode, beta, relu);
}

#define GS(p, sym) do { void* _t = 0; cudaGetSymbolAddress(&_t, sym); p = (float*)_t; } while (0)

extern "C" void kernel_launch(void* const* d_in, const int* in_sizes, int n_in,
                              void* d_out, int out_size)
{
    const float* adj      = (const float*)d_in[0];
    const float* inputs   = (const float*)d_in[1];
    const float* W0_w     = (const float*)d_in[3];
    const float* W0_b     = (const float*)d_in[4];
    const float* W1_w     = (const float*)d_in[5];
    const float* W1_b     = (const float*)d_in[6];
    const float* linc_w   = (const float*)d_in[7];
    const float* linc_b   = (const float*)d_in[8];
    const float* fc1_w    = (const float*)d_in[9];
    const float* fc2_w    = (const float*)d_in[10];
    const float* conv_w   = (const float*)d_in[11];
    const float* conv_b   = (const float*)d_in[12];
    const float* aq_w     = (const float*)d_in[13];
    const float* aq_b     = (const float*)d_in[14];
    const float* ak_w     = (const float*)d_in[15];
    const float* ak_b     = (const float*)d_in[16];
    float* out = (float*)d_out;

    float *pax, *pt1, *pt2, *pout1, *pconve, *pwk, *px, *pq, *pk, *pattn, *pout3, *phbuf;
    GS(pax, g_ax); GS(pt1, g_t1); GS(pt2, g_t2); GS(pout1, g_out1);
    GS(pconve, g_conve); GS(pwk, g_wk); GS(px, g_x); GS(pq, g_q); GS(pk, g_k);
    GS(pattn, g_attn); GS(pout3, g_out3); GS(phbuf, g_hbuf);

    const long long sND = (long long)cN * cD;        // 786432
    const long long sNX = (long long)cN * cX;
    const long long sNN = (long long)cN * cN;

    // 1) denom = adj.sum(2) + 1
    denom_kernel<<<NB, 256>>>(adj);

    // 2) Ax = adj @ inputs  (8 batches, NN layout)
    run_gemm(1, dim3(cD/128, cN/128, cB), adj, inputs, pax,
             cN, cD, cN, cN, cD, cD, 1, sNN, 0, sND, 0, sND, 0,
             1.f, 0, 0, 0, 0);

    // 3) t1 = Ax @ W0^T + b ; 4) t2 = inputs @ W0^T + b
    run_gemm(0, dim3(cD/128, NB/128, 1), pax, W0_w, pt1,
             NB, cD, cD, cD, cD, cD, 1, 0,0,0,0,0,0, 1.f, W0_b, 0, 0, 0);
    run_gemm(0, dim3(cD/128, NB/128, 1), inputs, W0_w, pt2,
             NB, cD, cD, cD, cD, cD, 1, 0,0,0,0,0,0, 1.f, W0_b, 0, 0, 0);

    // 5) out1 = relu(t1/denom) + t2
    combine1_kernel<<<NB*cD/256, 256>>>();

    // 6) conv: repack weights, 3 accumulated GEMMs (bias on k=0, relu on k=2)
    repack_kernel<<<(cN*cN)/256, 256>>>(conv_w);
    for (int kk = 0; kk < 3; kk++)
        run_gemm(1, dim3(6, cN/128, cB), pwk + (long long)kk*cN*cN, pout1 + kk, pconve,
                 cN, cD-2, cN, cN, cD, cD, 1, 0, 0, sND, 0, sND, 0,
                 1.f, (kk==0) ? conv_b : 0, 1, (kk>0), (kk==2));

    // 7) x = concat([inputs, linearc(conve)], -1)
    copyx_kernel<<<NB*cD/256, 256>>>(inputs);
    run_gemm(0, dim3(cD/128, NB/128, 1), pconve, linc_w, px + cD,
             NB, cD, cD-2, cD, cD-2, cX, 1, 0,0,0,0,0,0, 1.f, linc_b, 0, 0, 0);

    // 8) q, k projections
    run_gemm(0, dim3(cX/128, NB/128, 1), px, aq_w, pq,
             NB, cX, cX, cX, cX, cX, 1, 0,0,0,0,0,0, 1.f, aq_b, 0, 0, 0);
    run_gemm(0, dim3(cX/128, NB/128, 1), px, ak_w, pk,
             NB, cX, cX, cX, cX, cX, 1, 0,0,0,0,0,0, 1.f, ak_b, 0, 0, 0);

    // 9) scores: 24 (b,h) GEMMs in one launch, z = b*3+h
    run_gemm(0, dim3(cN/128, cN/128, cB*cH), pq, pk, pattn,
             cN, cN, 512, cX, cX, cN, cH,
             sNX, 512, sNX, 512, (long long)cH*sNN, sNN,
             0.044194173824159216f, 0, 0, 0, 0);

    // 10) softmax rows + rowsums + head sums + head choice
    softmax_kernel<<<cB*cH*cN, 256>>>();
    headsum_kernel<<<cB*cH, 256>>>();
    choose_kernel<<<1, 32>>>();

    // 11) global top-2 threshold + sparse adj2 edge list
    top2a_kernel<<<cB*32, 256>>>();
    top2b_kernel<<<cB, 32>>>();
    build_kernel<<<cB*32, 256>>>();
    process_kernel<<<cB, 32>>>();

    // 12) dense part of GCN layer 2: out3 = x @ W1^T + b
    run_gemm(0, dim3(cD/128, NB/128, 1), px, W1_w, pout3,
             NB, cD, cX, cX, cX, cD, 1, 0,0,0,0,0,0, 1.f, W1_b, 0, 0, 0);

    // 13) sparse correction: out3[row] += relu((adj2@x @ W1^T + b)/denom2)
    sparse_ax_kernel<<<cB*LISTCAP, 256>>>();
    sparse_fix_kernel<<<cB*LISTCAP, 256>>>(W1_w, W1_b);

    // 14) fc: out = fc2( relu(fc1(out3)) )
    run_gemm(0, dim3(cD/128, NB/128, 1), pout3, fc1_w, phbuf,
             NB, cD, cD, cD, cD, cD, 1, 0,0,0,0,0,0, 1.f, 0, 0, 0, 1);
    run_gemm(0, dim3(cD/128, NB/128, 1), phbuf, fc2_w, out,
             NB, cD, cD, cD, cD, cD, 1, 0,0,0,0,0,0, 1.f, 0, 0, 0, 0);
}